// round 14
// baseline (speedup 1.0000x reference)
#include <cuda_runtime.h>

#define NN 100000
#define EE 800000
#define SCAN_NB 98   // 98*1024 = 100352 >= NN

typedef unsigned long long ull;

// ---------------- scratch (device globals) ----------------
__device__ float g_h1[NN * 64];
__device__ float g_h2[NN * 64];
__device__ float g_h3[NN * 64];
__device__ float g_asrc[NN * 2];
__device__ float g_adst[NN * 2];
__device__ float g_Wn[3][4096];
__device__ float g_We[3][320];
__device__ float g_bp[3][64];
__device__ float g_Wstk[8192];     // [k][c]: k<64 -> Wg[k][c] ; k>=64 -> Wg[k-64][64+c]
__device__ float g_avec[256];      // avS0[64] avS1[64] avD0[64] avD1[64]
__device__ int g_cnt[NN];
__device__ int g_rowptr[NN + 4];
__device__ int g_csr_src[EE];
__device__ int g_csr_eid[EE];
__device__ float g_S[NN * 5];
__device__ int g_scanflag[SCAN_NB];   // 0 = not ready; else block_total + 1

__device__ __forceinline__ float lrelu(float x) { return x > 0.f ? x : 0.2f * x; }

__device__ __forceinline__ ull pk2(float x) {
    ull r; asm("mov.b64 %0,{%1,%1};" : "=l"(r) : "f"(x)); return r;
}
__device__ __forceinline__ void fma2(ull& d, ull a, ull b) {
    asm("fma.rn.f32x2 %0,%1,%2,%0;" : "+l"(d) : "l"(a), "l"(b));
}
__device__ __forceinline__ float2 up2(ull v) {
    float2 r; asm("mov.b64 {%0,%1},%2;" : "=f"(r.x), "=f"(r.y) : "l"(v)); return r;
}

// ---------------- zero scratch that must be reset each call ----------------
__global__ void zero_all(int4* __restrict__ cnt4, int* __restrict__ flag) {
    int i = blockIdx.x * blockDim.x + threadIdx.x;
    if (i < NN / 4) cnt4[i] = make_int4(0, 0, 0, 0);
    if (i < SCAN_NB) flag[i] = 0;
}

// ---------------- count (blocks 0..781) + weight fold (blocks 782..913) ----------------
struct FoldW { const float* w[18]; const float* wg; const float* as; const float* ad; };

__global__ void count_fold(const int* __restrict__ dst, int* __restrict__ cnt,
                           FoldW fw, float* __restrict__ Wn, float* __restrict__ We,
                           float* __restrict__ bp, float* __restrict__ Wstk,
                           float* __restrict__ avec) {
    int b = blockIdx.x;
    if (b < 782) {
        int i = b * 256 + threadIdx.x;
        if (i * 4 >= EE) return;
        int4 d = ((const int4*)dst)[i];
        atomicAdd(&cnt[d.x], 1);
        atomicAdd(&cnt[d.y], 1);
        atomicAdd(&cnt[d.z], 1);
        atomicAdd(&cnt[d.w], 1);
        return;
    }
    int fb = b - 782;
    int L = fb / 33;
    int t = (fb % 33) * 256 + threadIdx.x;
    if (L < 3) {
        if (t >= 4480) return;
        const float* wn = fw.w[6 * L + 0];
        const float* bn = fw.w[6 * L + 1];
        const float* we = fw.w[6 * L + 2];
        const float* be = fw.w[6 * L + 3];
        const float* wc = fw.w[6 * L + 4];
        const float* bc = fw.w[6 * L + 5];
        if (t < 4096) {
            int r = t >> 6, c = t & 63;
            float s = 0.f;
            #pragma unroll 8
            for (int k = 0; k < 64; k++) s += wn[r * 64 + k] * wc[k * 64 + c];
            Wn[L * 4096 + t] = s;
        } else if (t < 4416) {
            int u = t - 4096;
            int j = u >> 6, c = u & 63;
            float s = 0.f;
            #pragma unroll 8
            for (int k = 0; k < 64; k++) s += we[j * 64 + k] * wc[(64 + k) * 64 + c];
            We[L * 320 + u] = s;
        } else {
            int c = t - 4416;
            float s = bc[c];
            #pragma unroll 8
            for (int k = 0; k < 64; k++)
                s += bn[k] * wc[k * 64 + c] + be[k] * wc[(64 + k) * 64 + c];
            bp[L * 64 + c] = s;
        }
    } else {
        if (t < 8192) {
            int k = t >> 6, c = t & 63;
            Wstk[t] = (k < 64) ? fw.wg[k * 128 + c] : fw.wg[(k - 64) * 128 + 64 + c];
        } else if (t < 8448) {
            int u = t - 8192;
            int vec = u >> 6;
            int k = u & 63;
            int hd = vec & 1;
            const float* att = (vec < 2) ? fw.as : fw.ad;
            float s = 0.f;
            #pragma unroll 8
            for (int c = 0; c < 64; c++) s += fw.wg[k * 128 + hd * 64 + c] * att[hd * 64 + c];
            avec[u] = s;
        }
    }
}

// ---------------- single-kernel scan (all 98 blocks resident; flag = total+1) ----------------
__global__ void scan_lb(const int* __restrict__ cnt, int* __restrict__ flag,
                        int* __restrict__ rowptr) {
    __shared__ int wsum[8];
    __shared__ int offsum[8];
    __shared__ int s_boff;
    int b = blockIdx.x, t = threadIdx.x;
    int lane = t & 31, wid = t >> 5;
    int idx = b * 1024 + t * 4;
    int v[4] = {0, 0, 0, 0};
    if (idx < NN) {
        int4 d = *(const int4*)(cnt + idx);
        v[0] = d.x; v[1] = d.y; v[2] = d.z; v[3] = d.w;
    }
    #pragma unroll
    for (int j = 1; j < 4; j++) v[j] += v[j - 1];
    int tot = v[3];
    int incl = tot;
    #pragma unroll
    for (int o = 1; o < 32; o <<= 1) {
        int u = __shfl_up_sync(0xffffffffu, incl, o);
        if (lane >= o) incl += u;
    }
    if (lane == 31) wsum[wid] = incl;
    __syncthreads();
    if (t == 0) {
        int bt = 0;
        #pragma unroll
        for (int w = 0; w < 8; w++) bt += wsum[w];
        atomicExch(&flag[b], bt + 1);
    }
    int agg = 0;
    if (t < b) {
        volatile int* vf = (volatile int*)flag;
        int val;
        do { val = vf[t]; } while (val == 0);
        agg = val - 1;
    }
    #pragma unroll
    for (int o = 16; o; o >>= 1) agg += __shfl_xor_sync(0xffffffffu, agg, o);
    if (lane == 0) offsum[wid] = agg;
    __syncthreads();
    if (t == 0) {
        int bo = 0;
        #pragma unroll
        for (int w = 0; w < 8; w++) bo += offsum[w];
        s_boff = bo;
    }
    __syncthreads();
    int woff = 0;
    for (int w = 0; w < wid; w++) woff += wsum[w];
    int excl = s_boff + woff + incl - tot;
    if (idx < NN) {
        #pragma unroll
        for (int j = 0; j < 4; j++) rowptr[idx + j + 1] = excl + v[j];
    }
    if (b == 0 && t == 0) rowptr[0] = 0;
}

// ---------------- scatter: countdown atomic + plain stores ----------------
__device__ __forceinline__ void scat1(int d, int s, int e, const int* __restrict__ rowptr,
                                      int* __restrict__ cnt, int* __restrict__ csr_src,
                                      int* __restrict__ csr_eid) {
    int pos = atomicAdd(&cnt[d], -1) - 1;
    int slot = rowptr[d] + pos;
    csr_src[slot] = s;
    csr_eid[slot] = e;
}

__global__ void scatter_kernel(const int* __restrict__ src, const int* __restrict__ dst,
                               const int* __restrict__ rowptr, int* __restrict__ cnt,
                               int* __restrict__ csr_src, int* __restrict__ csr_eid) {
    int i = blockIdx.x * blockDim.x + threadIdx.x;
    if (i * 4 >= EE) return;
    int4 d4 = ((const int4*)dst)[i];
    int4 s4 = ((const int4*)src)[i];
    int e = i * 4;
    scat1(d4.x, s4.x, e + 0, rowptr, cnt, csr_src, csr_eid);
    scat1(d4.y, s4.y, e + 1, rowptr, cnt, csr_src, csr_eid);
    scat1(d4.z, s4.z, e + 2, rowptr, cnt, csr_src, csr_eid);
    scat1(d4.w, s4.w, e + 3, rowptr, cnt, csr_src, csr_eid);
}

// ---------------- fused layer ----------------
// sflag=1 (L1): compute S[n] = Σ ea[eid] in-kernel (lane-parallel), use + store for L2/L3.
// sflag=0: read precomputed S.
__global__ __launch_bounds__(256) void fused_layer(
    const float* __restrict__ hin, const int* __restrict__ csr_src,
    const int* __restrict__ csr_eid, const int* __restrict__ rowptr,
    const float* __restrict__ ea, float* __restrict__ S,
    const float* __restrict__ Wn, const float* __restrict__ We,
    const float* __restrict__ bp, float* __restrict__ out, int relu, int sflag,
    int attn, const float* __restrict__ avec,
    float* __restrict__ aS, float* __restrict__ aD) {
    __shared__ float qT[70][68];
    __shared__ float Ws[70][64];
    __shared__ float sAv[256];
    int t = threadIdx.x;
    int n0 = blockIdx.x << 6;

    #pragma unroll
    for (int i = 0; i < 5; i++) {
        int idx = t + i * 256;
        if (idx < 1120) {
            int r = idx >> 4, c4 = (idx & 15) << 2;
            float4 v;
            if (r < 64) v = *(const float4*)(Wn + r * 64 + c4);
            else if (r < 69) v = *(const float4*)(We + (r - 64) * 64 + c4);
            else v = *(const float4*)(bp + c4);
            *(float4*)&Ws[r][c4] = v;
        }
    }
    if (attn) sAv[t] = avec[t];

    int w = t >> 5, lane = t & 31;
    #pragma unroll
    for (int i = 0; i < 8; i++) {
        int nl = w * 8 + i;
        int n = n0 + nl;
        float q0 = 0.f, q1 = 0.f, deg = 0.f;
        if (n < NN) {
            int start = rowptr[n], end = rowptr[n + 1];
            deg = (float)(end - start);
            int j = start;
            for (; j + 3 < end; j += 4) {
                const float* pa = hin + (size_t)csr_src[j] * 64;
                const float* pb = hin + (size_t)csr_src[j + 1] * 64;
                const float* pc = hin + (size_t)csr_src[j + 2] * 64;
                const float* pd = hin + (size_t)csr_src[j + 3] * 64;
                float a0 = pa[lane], a1 = pa[lane + 32];
                float b0 = pb[lane], b1 = pb[lane + 32];
                float c0v = pc[lane], c1 = pc[lane + 32];
                float d0 = pd[lane], d1 = pd[lane + 32];
                if (relu) {
                    a0 = fmaxf(a0, 0.f); a1 = fmaxf(a1, 0.f);
                    b0 = fmaxf(b0, 0.f); b1 = fmaxf(b1, 0.f);
                    c0v = fmaxf(c0v, 0.f); c1 = fmaxf(c1, 0.f);
                    d0 = fmaxf(d0, 0.f); d1 = fmaxf(d1, 0.f);
                }
                q0 += (a0 + b0) + (c0v + d0);
                q1 += (a1 + b1) + (c1 + d1);
            }
            for (; j < end; j++) {
                const float* pa = hin + (size_t)csr_src[j] * 64;
                float a0 = pa[lane], a1 = pa[lane + 32];
                if (relu) { a0 = fmaxf(a0, 0.f); a1 = fmaxf(a1, 0.f); }
                q0 += a0;
                q1 += a1;
            }
            if (sflag) {
                // lane-parallel ea gather + reduce; store S for later layers
                float s0 = 0.f, s1 = 0.f, s2 = 0.f, s3 = 0.f, s4 = 0.f;
                for (int jj = start + lane; jj < end; jj += 32) {
                    const float* e = ea + (size_t)csr_eid[jj] * 5;
                    s0 += e[0]; s1 += e[1]; s2 += e[2]; s3 += e[3]; s4 += e[4];
                }
                #pragma unroll
                for (int o = 16; o; o >>= 1) {
                    s0 += __shfl_xor_sync(0xffffffffu, s0, o);
                    s1 += __shfl_xor_sync(0xffffffffu, s1, o);
                    s2 += __shfl_xor_sync(0xffffffffu, s2, o);
                    s3 += __shfl_xor_sync(0xffffffffu, s3, o);
                    s4 += __shfl_xor_sync(0xffffffffu, s4, o);
                }
                if (lane == 0) {
                    qT[64][nl] = s0; qT[65][nl] = s1; qT[66][nl] = s2;
                    qT[67][nl] = s3; qT[68][nl] = s4;
                    S[(size_t)n * 5 + 0] = s0; S[(size_t)n * 5 + 1] = s1;
                    S[(size_t)n * 5 + 2] = s2; S[(size_t)n * 5 + 3] = s3;
                    S[(size_t)n * 5 + 4] = s4;
                }
            } else {
                if (lane < 5) qT[64 + lane][nl] = S[(size_t)n * 5 + lane];
            }
        } else {
            if (lane < 5) qT[64 + lane][nl] = 0.f;
        }
        qT[lane][nl] = q0;
        qT[lane + 32][nl] = q1;
        if (lane == 5) qT[69][nl] = deg;
    }
    __syncthreads();

    int tcol = t & 15, trow = t >> 4;
    int r0 = trow << 2, c0 = tcol << 2;
    ull acc[4][2];
    #pragma unroll
    for (int i = 0; i < 4; i++) { acc[i][0] = 0ull; acc[i][1] = 0ull; }

    #pragma unroll 10
    for (int k = 0; k < 70; k++) {
        float4 a = *(float4*)&qT[k][r0];
        const ull* bb = (const ull*)&Ws[k][c0];
        ull b0 = bb[0], b1 = bb[1];
        ull a0 = pk2(a.x), a1 = pk2(a.y), a2 = pk2(a.z), a3 = pk2(a.w);
        fma2(acc[0][0], a0, b0); fma2(acc[0][1], a0, b1);
        fma2(acc[1][0], a1, b0); fma2(acc[1][1], a1, b1);
        fma2(acc[2][0], a2, b0); fma2(acc[2][1], a2, b1);
        fma2(acc[3][0], a3, b0); fma2(acc[3][1], a3, b1);
    }

    #pragma unroll
    for (int i = 0; i < 4; i++) {
        int n = n0 + r0 + i;
        float2 p0 = up2(acc[i][0]), p1 = up2(acc[i][1]);
        if (n < NN)
            *(float4*)(out + (size_t)n * 64 + c0) = make_float4(p0.x, p0.y, p1.x, p1.y);
        if (attn) {
            float r0v = fmaxf(p0.x, 0.f), r1v = fmaxf(p0.y, 0.f);
            float r2v = fmaxf(p1.x, 0.f), r3v = fmaxf(p1.y, 0.f);
            float pS0 = r0v * sAv[c0] + r1v * sAv[c0 + 1] + r2v * sAv[c0 + 2] + r3v * sAv[c0 + 3];
            float pS1 = r0v * sAv[64 + c0] + r1v * sAv[64 + c0 + 1] + r2v * sAv[64 + c0 + 2] + r3v * sAv[64 + c0 + 3];
            float pD0 = r0v * sAv[128 + c0] + r1v * sAv[128 + c0 + 1] + r2v * sAv[128 + c0 + 2] + r3v * sAv[128 + c0 + 3];
            float pD1 = r0v * sAv[192 + c0] + r1v * sAv[192 + c0 + 1] + r2v * sAv[192 + c0 + 2] + r3v * sAv[192 + c0 + 3];
            #pragma unroll
            for (int o = 1; o < 16; o <<= 1) {
                pS0 += __shfl_xor_sync(0xffffffffu, pS0, o);
                pS1 += __shfl_xor_sync(0xffffffffu, pS1, o);
                pD0 += __shfl_xor_sync(0xffffffffu, pD0, o);
                pD1 += __shfl_xor_sync(0xffffffffu, pD1, o);
            }
            if (tcol == 0 && n < NN) {
                aS[n * 2] = pS0; aS[n * 2 + 1] = pS1;
                aD[n * 2] = pD0; aD[n * 2 + 1] = pD1;
            }
        }
    }
}

// ---------------- fused GAT: weighted gather -> smem zT -> mini-GEMM -> out ----------------
__global__ __launch_bounds__(256) void gat_fused(
    const int* __restrict__ csr_src, const int* __restrict__ rowptr,
    const float2* __restrict__ aS, const float2* __restrict__ aD,
    const float* __restrict__ h, const float* __restrict__ Wstk,
    const float* __restrict__ bias, float* __restrict__ out) {
    extern __shared__ float sm[];
    float* zT = sm;            // [128][68]
    float* Wc = sm + 128 * 68; // [64][64]
    int t = threadIdx.x;
    int n0 = blockIdx.x << 6;

    #pragma unroll
    for (int i = 0; i < 4; i++) {
        int idx = t + i * 256;
        int r = idx >> 4, c4 = (idx & 15) << 2;
        *(float4*)&Wc[r * 64 + c4] = *(const float4*)(Wstk + r * 64 + c4);
    }

    int w = t >> 5, lane = t & 31;
    #pragma unroll
    for (int i = 0; i < 8; i++) {
        int nl = w * 8 + i;
        int n = n0 + nl;
        float acc0 = 0.f, acc1 = 0.f, acc2 = 0.f, acc3 = 0.f;
        float id0 = 0.f, id1 = 0.f;
        if (n < NN) {
            int start = rowptr[n], end = rowptr[n + 1];
            float2 ad = aD[n];
            float m0 = -1e30f, m1 = -1e30f;
            for (int j = start + lane; j < end; j += 32) {
                float2 as = aS[csr_src[j]];
                m0 = fmaxf(m0, lrelu(as.x + ad.x));
                m1 = fmaxf(m1, lrelu(as.y + ad.y));
            }
            #pragma unroll
            for (int o = 16; o; o >>= 1) {
                m0 = fmaxf(m0, __shfl_xor_sync(0xffffffffu, m0, o));
                m1 = fmaxf(m1, __shfl_xor_sync(0xffffffffu, m1, o));
            }
            float den0 = 0.f, den1 = 0.f;
            int j = start;
            for (; j + 1 < end; j += 2) {
                int sA = csr_src[j], sB = csr_src[j + 1];
                float2 aA = aS[sA], aB = aS[sB];
                const float* hA = h + (size_t)sA * 64;
                const float* hB = h + (size_t)sB * 64;
                float vA0 = fmaxf(hA[lane], 0.f), vA1 = fmaxf(hA[lane + 32], 0.f);
                float vB0 = fmaxf(hB[lane], 0.f), vB1 = fmaxf(hB[lane + 32], 0.f);
                float wA0 = __expf(lrelu(aA.x + ad.x) - m0);
                float wA1 = __expf(lrelu(aA.y + ad.y) - m1);
                float wB0 = __expf(lrelu(aB.x + ad.x) - m0);
                float wB1 = __expf(lrelu(aB.y + ad.y) - m1);
                den0 += wA0 + wB0;
                den1 += wA1 + wB1;
                acc0 += wA0 * vA0 + wB0 * vB0;
                acc1 += wA0 * vA1 + wB0 * vB1;
                acc2 += wA1 * vA0 + wB1 * vB0;
                acc3 += wA1 * vA1 + wB1 * vB1;
            }
            if (j < end) {
                int sA = csr_src[j];
                float2 aA = aS[sA];
                const float* hA = h + (size_t)sA * 64;
                float vA0 = fmaxf(hA[lane], 0.f), vA1 = fmaxf(hA[lane + 32], 0.f);
                float wA0 = __expf(lrelu(aA.x + ad.x) - m0);
                float wA1 = __expf(lrelu(aA.y + ad.y) - m1);
                den0 += wA0;
                den1 += wA1;
                acc0 += wA0 * vA0;
                acc1 += wA0 * vA1;
                acc2 += wA1 * vA0;
                acc3 += wA1 * vA1;
            }
            id0 = 0.5f / (den0 + 1e-16f);
            id1 = 0.5f / (den1 + 1e-16f);
        }
        zT[(size_t)lane * 68 + nl] = acc0 * id0;
        zT[(size_t)(lane + 32) * 68 + nl] = acc1 * id0;
        zT[(size_t)(lane + 64) * 68 + nl] = acc2 * id1;
        zT[(size_t)(lane + 96) * 68 + nl] = acc3 * id1;
    }
    __syncthreads();

    int tcol = t & 15, trow = t >> 4;
    int r0 = trow << 2, c0 = tcol << 2;
    ull acc[4][2];
    #pragma unroll
    for (int i = 0; i < 4; i++) { acc[i][0] = 0ull; acc[i][1] = 0ull; }

    #pragma unroll 8
    for (int k = 0; k < 64; k++) {
        float4 a = *(float4*)&zT[k * 68 + r0];
        const ull* bb = (const ull*)&Wc[k * 64 + c0];
        ull b0 = bb[0], b1 = bb[1];
        ull a0 = pk2(a.x), a1 = pk2(a.y), a2 = pk2(a.z), a3 = pk2(a.w);
        fma2(acc[0][0], a0, b0); fma2(acc[0][1], a0, b1);
        fma2(acc[1][0], a1, b0); fma2(acc[1][1], a1, b1);
        fma2(acc[2][0], a2, b0); fma2(acc[2][1], a2, b1);
        fma2(acc[3][0], a3, b0); fma2(acc[3][1], a3, b1);
    }
    __syncthreads();
    #pragma unroll
    for (int i = 0; i < 4; i++) {
        int idx = t + i * 256;
        int r = idx >> 4, c4 = (idx & 15) << 2;
        *(float4*)&Wc[r * 64 + c4] = *(const float4*)(Wstk + (64 + r) * 64 + c4);
    }
    __syncthreads();
    #pragma unroll 8
    for (int k = 0; k < 64; k++) {
        float4 a = *(float4*)&zT[(64 + k) * 68 + r0];
        const ull* bb = (const ull*)&Wc[k * 64 + c0];
        ull b0 = bb[0], b1 = bb[1];
        ull a0 = pk2(a.x), a1 = pk2(a.y), a2 = pk2(a.z), a3 = pk2(a.w);
        fma2(acc[0][0], a0, b0); fma2(acc[0][1], a0, b1);
        fma2(acc[1][0], a1, b0); fma2(acc[1][1], a1, b1);
        fma2(acc[2][0], a2, b0); fma2(acc[2][1], a2, b1);
        fma2(acc[3][0], a3, b0); fma2(acc[3][1], a3, b1);
    }

    float4 bv = *(const float4*)(bias + c0);
    #pragma unroll
    for (int i = 0; i < 4; i++) {
        int n = n0 + r0 + i;
        if (n < NN) {
            float2 p0 = up2(acc[i][0]), p1 = up2(acc[i][1]);
            *(float4*)(out + (size_t)n * 64 + c0) =
                make_float4(p0.x + bv.x, p0.y + bv.y, p1.x + bv.z, p1.y + bv.w);
        }
    }
}

// ---------------- launch ----------------
extern "C" void kernel_launch(void* const* d_in, const int* in_sizes, int n_in,
                              void* d_out, int out_size) {
    const float* x = (const float*)d_in[0];
    const int* ei = (const int*)d_in[1];
    const float* ea = (const float*)d_in[2];
    const int* src = ei;
    const int* dst = ei + EE;
    FoldW fw;
    for (int i = 0; i < 18; i++) fw.w[i] = (const float*)d_in[3 + i];
    fw.wg = (const float*)d_in[21];
    fw.as = (const float*)d_in[22];
    fw.ad = (const float*)d_in[23];
    const float* b_gat = (const float*)d_in[24];
    float* out = (float*)d_out;

    float *h1, *h2, *h3, *asrc, *adst, *Wn, *We, *bp, *Wstk, *avec, *S;
    int *cnt, *rowptr, *csr_src, *csr_eid, *flag;
    cudaGetSymbolAddress((void**)&h1, g_h1);
    cudaGetSymbolAddress((void**)&h2, g_h2);
    cudaGetSymbolAddress((void**)&h3, g_h3);
    cudaGetSymbolAddress((void**)&asrc, g_asrc);
    cudaGetSymbolAddress((void**)&adst, g_adst);
    cudaGetSymbolAddress((void**)&Wn, g_Wn);
    cudaGetSymbolAddress((void**)&We, g_We);
    cudaGetSymbolAddress((void**)&bp, g_bp);
    cudaGetSymbolAddress((void**)&Wstk, g_Wstk);
    cudaGetSymbolAddress((void**)&avec, g_avec);
    cudaGetSymbolAddress((void**)&cnt, g_cnt);
    cudaGetSymbolAddress((void**)&rowptr, g_rowptr);
    cudaGetSymbolAddress((void**)&csr_src, g_csr_src);
    cudaGetSymbolAddress((void**)&csr_eid, g_csr_eid);
    cudaGetSymbolAddress((void**)&S, g_S);
    cudaGetSymbolAddress((void**)&flag, g_scanflag);

    static bool attr_done = false;
    if (!attr_done) {
        cudaFuncSetAttribute(gat_fused, cudaFuncAttributeMaxDynamicSharedMemorySize,
                             (128 * 68 + 64 * 64) * 4);
        attr_done = true;
    }

    const int FB = (NN + 63) / 64;   // 1563 blocks

    // ---- CSR build + weight folding ----
    zero_all<<<98, 256>>>((int4*)cnt, flag);
    count_fold<<<782 + 132, 256>>>(dst, cnt, fw, Wn, We, bp, Wstk, avec);
    scan_lb<<<SCAN_NB, 256>>>(cnt, flag, rowptr);
    scatter_kernel<<<(EE / 4 + 255) / 256, 256>>>(src, dst, rowptr, cnt, csr_src, csr_eid);

    // ---- 3 fused layers (L1 also computes + stores S) ----
    fused_layer<<<FB, 256>>>(x, csr_src, csr_eid, rowptr, ea, S,
                             Wn + 0 * 4096, We + 0 * 320, bp + 0 * 64, h1,
                             0, 1, 0, avec, nullptr, nullptr);
    fused_layer<<<FB, 256>>>(h1, csr_src, csr_eid, rowptr, ea, S,
                             Wn + 1 * 4096, We + 1 * 320, bp + 1 * 64, h2,
                             1, 0, 0, avec, nullptr, nullptr);
    fused_layer<<<FB, 256>>>(h2, csr_src, csr_eid, rowptr, ea, S,
                             Wn + 2 * 4096, We + 2 * 320, bp + 2 * 64, h3,
                             1, 0, 1, avec, asrc, adst);

    // ---- fused GAT tail ----
    gat_fused<<<FB, 256, (128 * 68 + 64 * 64) * 4>>>(
        csr_src, rowptr, (const float2*)asrc, (const float2*)adst,
        h3, Wstk, b_gat, out);
}

// round 15
// speedup vs baseline: 1.0588x; 1.0588x over previous
#include <cuda_runtime.h>

#define NN 100000
#define EE 800000
#define SCAN_NB 98   // 98*1024 = 100352 >= NN

typedef unsigned long long ull;

// ---------------- scratch (device globals) ----------------
__device__ float g_h1[NN * 64];
__device__ float g_h2[NN * 64];
__device__ float g_h3[NN * 64];
__device__ float g_asrc[NN * 2];
__device__ float g_adst[NN * 2];
__device__ float g_Wn[3][4096];
__device__ float g_We[3][320];
__device__ float g_bp[3][64];
__device__ float g_Wstk[8192];     // [k][c]: k<64 -> Wg[k][c] ; k>=64 -> Wg[k-64][64+c]
__device__ float g_avec[256];      // avS0[64] avS1[64] avD0[64] avD1[64]
__device__ int g_cnt[NN];
__device__ int g_rowptr[NN + 4];
__device__ int g_csr_src[EE];
__device__ float4 g_S4[NN * 2];    // S padded to 8 floats/node, 16B-aligned
__device__ int g_scanflag[SCAN_NB];

__device__ __forceinline__ float lrelu(float x) { return x > 0.f ? x : 0.2f * x; }

__device__ __forceinline__ ull pk2(float x) {
    ull r; asm("mov.b64 %0,{%1,%1};" : "=l"(r) : "f"(x)); return r;
}
__device__ __forceinline__ void fma2(ull& d, ull a, ull b) {
    asm("fma.rn.f32x2 %0,%1,%2,%0;" : "+l"(d) : "l"(a), "l"(b));
}
__device__ __forceinline__ float2 up2(ull v) {
    float2 r; asm("mov.b64 {%0,%1},%2;" : "=f"(r.x), "=f"(r.y) : "l"(v)); return r;
}

// ---------------- zero scratch that must be reset each call ----------------
__global__ void zero_all(int4* __restrict__ cnt4, float4* __restrict__ S4,
                         int* __restrict__ flag) {
    int i = blockIdx.x * blockDim.x + threadIdx.x;
    if (i < NN / 4) cnt4[i] = make_int4(0, 0, 0, 0);
    if (i < NN * 2) S4[i] = make_float4(0.f, 0.f, 0.f, 0.f);
    if (i < SCAN_NB) flag[i] = 0;
}

// ---------------- count (blocks 0..781) + weight fold (blocks 782..913) ----------------
struct FoldW { const float* w[18]; const float* wg; const float* as; const float* ad; };

__global__ void count_fold(const int* __restrict__ dst, int* __restrict__ cnt,
                           FoldW fw, float* __restrict__ Wn, float* __restrict__ We,
                           float* __restrict__ bp, float* __restrict__ Wstk,
                           float* __restrict__ avec) {
    int b = blockIdx.x;
    if (b < 782) {
        int i = b * 256 + threadIdx.x;
        if (i * 4 >= EE) return;
        int4 d = ((const int4*)dst)[i];
        atomicAdd(&cnt[d.x], 1);
        atomicAdd(&cnt[d.y], 1);
        atomicAdd(&cnt[d.z], 1);
        atomicAdd(&cnt[d.w], 1);
        return;
    }
    int fb = b - 782;
    int L = fb / 33;
    int t = (fb % 33) * 256 + threadIdx.x;
    if (L < 3) {
        if (t >= 4480) return;
        const float* wn = fw.w[6 * L + 0];
        const float* bn = fw.w[6 * L + 1];
        const float* we = fw.w[6 * L + 2];
        const float* be = fw.w[6 * L + 3];
        const float* wc = fw.w[6 * L + 4];
        const float* bc = fw.w[6 * L + 5];
        if (t < 4096) {
            int r = t >> 6, c = t & 63;
            float s = 0.f;
            #pragma unroll 8
            for (int k = 0; k < 64; k++) s += wn[r * 64 + k] * wc[k * 64 + c];
            Wn[L * 4096 + t] = s;
        } else if (t < 4416) {
            int u = t - 4096;
            int j = u >> 6, c = u & 63;
            float s = 0.f;
            #pragma unroll 8
            for (int k = 0; k < 64; k++) s += we[j * 64 + k] * wc[(64 + k) * 64 + c];
            We[L * 320 + u] = s;
        } else {
            int c = t - 4416;
            float s = bc[c];
            #pragma unroll 8
            for (int k = 0; k < 64; k++)
                s += bn[k] * wc[k * 64 + c] + be[k] * wc[(64 + k) * 64 + c];
            bp[L * 64 + c] = s;
        }
    } else {
        if (t < 8192) {
            int k = t >> 6, c = t & 63;
            Wstk[t] = (k < 64) ? fw.wg[k * 128 + c] : fw.wg[(k - 64) * 128 + 64 + c];
        } else if (t < 8448) {
            int u = t - 8192;
            int vec = u >> 6;
            int k = u & 63;
            int hd = vec & 1;
            const float* att = (vec < 2) ? fw.as : fw.ad;
            float s = 0.f;
            #pragma unroll 8
            for (int c = 0; c < 64; c++) s += fw.wg[k * 128 + hd * 64 + c] * att[hd * 64 + c];
            avec[u] = s;
        }
    }
}

// ---------------- single-kernel scan ----------------
__global__ void scan_lb(const int* __restrict__ cnt, int* __restrict__ flag,
                        int* __restrict__ rowptr) {
    __shared__ int wsum[8];
    __shared__ int offsum[8];
    __shared__ int s_boff;
    int b = blockIdx.x, t = threadIdx.x;
    int lane = t & 31, wid = t >> 5;
    int idx = b * 1024 + t * 4;
    int v[4] = {0, 0, 0, 0};
    if (idx < NN) {
        int4 d = *(const int4*)(cnt + idx);
        v[0] = d.x; v[1] = d.y; v[2] = d.z; v[3] = d.w;
    }
    #pragma unroll
    for (int j = 1; j < 4; j++) v[j] += v[j - 1];
    int tot = v[3];
    int incl = tot;
    #pragma unroll
    for (int o = 1; o < 32; o <<= 1) {
        int u = __shfl_up_sync(0xffffffffu, incl, o);
        if (lane >= o) incl += u;
    }
    if (lane == 31) wsum[wid] = incl;
    __syncthreads();
    if (t == 0) {
        int bt = 0;
        #pragma unroll
        for (int w = 0; w < 8; w++) bt += wsum[w];
        atomicExch(&flag[b], bt + 1);
    }
    int agg = 0;
    if (t < b) {
        volatile int* vf = (volatile int*)flag;
        int val;
        do { val = vf[t]; } while (val == 0);
        agg = val - 1;
    }
    #pragma unroll
    for (int o = 16; o; o >>= 1) agg += __shfl_xor_sync(0xffffffffu, agg, o);
    if (lane == 0) offsum[wid] = agg;
    __syncthreads();
    if (t == 0) {
        int bo = 0;
        #pragma unroll
        for (int w = 0; w < 8; w++) bo += offsum[w];
        s_boff = bo;
    }
    __syncthreads();
    int woff = 0;
    for (int w = 0; w < wid; w++) woff += wsum[w];
    int excl = s_boff + woff + incl - tot;
    if (idx < NN) {
        #pragma unroll
        for (int j = 0; j < 4; j++) rowptr[idx + j + 1] = excl + v[j];
    }
    if (b == 0 && t == 0) rowptr[0] = 0;
}

// ---------------- scatter: countdown + csr_src store + vectorized S reduction ----------------
__device__ __forceinline__ void scat1(int d, int s, int e, const int* __restrict__ rowptr,
                                      int* __restrict__ cnt, int* __restrict__ csr_src,
                                      const float* __restrict__ ea, float* __restrict__ S8) {
    int pos = atomicAdd(&cnt[d], -1) - 1;
    csr_src[rowptr[d] + pos] = s;
    const float* eap = ea + (size_t)e * 5;
    float e0 = eap[0], e1 = eap[1], e2 = eap[2], e3 = eap[3], e4 = eap[4];
    float* sp = S8 + (size_t)d * 8;
    asm volatile("red.global.add.v4.f32 [%0], {%1,%2,%3,%4};"
                 :: "l"(sp), "f"(e0), "f"(e1), "f"(e2), "f"(e3) : "memory");
    atomicAdd(sp + 4, e4);
}

__global__ void scatter_kernel(const int* __restrict__ src, const int* __restrict__ dst,
                               const int* __restrict__ rowptr, int* __restrict__ cnt,
                               int* __restrict__ csr_src, const float* __restrict__ ea,
                               float* __restrict__ S8) {
    int i = blockIdx.x * blockDim.x + threadIdx.x;
    if (i * 4 >= EE) return;
    int4 d4 = ((const int4*)dst)[i];
    int4 s4 = ((const int4*)src)[i];
    int e = i * 4;
    scat1(d4.x, s4.x, e + 0, rowptr, cnt, csr_src, ea, S8);
    scat1(d4.y, s4.y, e + 1, rowptr, cnt, csr_src, ea, S8);
    scat1(d4.z, s4.z, e + 2, rowptr, cnt, csr_src, ea, S8);
    scat1(d4.w, s4.w, e + 3, rowptr, cnt, csr_src, ea, S8);
}

// ---------------- fused layer (R12-proven; S stride 8) ----------------
__global__ __launch_bounds__(256) void fused_layer(
    const float* __restrict__ hin, const int* __restrict__ csr_src,
    const int* __restrict__ rowptr, const float* __restrict__ S8,
    const float* __restrict__ Wn, const float* __restrict__ We,
    const float* __restrict__ bp, float* __restrict__ out, int relu,
    int attn, const float* __restrict__ avec,
    float* __restrict__ aS, float* __restrict__ aD) {
    __shared__ float qT[70][68];
    __shared__ float Ws[70][64];
    __shared__ float sAv[256];
    int t = threadIdx.x;
    int n0 = blockIdx.x << 6;

    #pragma unroll
    for (int i = 0; i < 5; i++) {
        int idx = t + i * 256;
        if (idx < 1120) {
            int r = idx >> 4, c4 = (idx & 15) << 2;
            float4 v;
            if (r < 64) v = *(const float4*)(Wn + r * 64 + c4);
            else if (r < 69) v = *(const float4*)(We + (r - 64) * 64 + c4);
            else v = *(const float4*)(bp + c4);
            *(float4*)&Ws[r][c4] = v;
        }
    }
    if (attn) sAv[t] = avec[t];

    int w = t >> 5, lane = t & 31;
    #pragma unroll
    for (int i = 0; i < 8; i++) {
        int nl = w * 8 + i;
        int n = n0 + nl;
        float q0 = 0.f, q1 = 0.f, deg = 0.f, sv = 0.f;
        if (n < NN) {
            int start = rowptr[n], end = rowptr[n + 1];
            deg = (float)(end - start);
            int j = start;
            for (; j + 3 < end; j += 4) {
                const float* pa = hin + (size_t)csr_src[j] * 64;
                const float* pb = hin + (size_t)csr_src[j + 1] * 64;
                const float* pc = hin + (size_t)csr_src[j + 2] * 64;
                const float* pd = hin + (size_t)csr_src[j + 3] * 64;
                float a0 = pa[lane], a1 = pa[lane + 32];
                float b0 = pb[lane], b1 = pb[lane + 32];
                float c0v = pc[lane], c1 = pc[lane + 32];
                float d0 = pd[lane], d1 = pd[lane + 32];
                if (relu) {
                    a0 = fmaxf(a0, 0.f); a1 = fmaxf(a1, 0.f);
                    b0 = fmaxf(b0, 0.f); b1 = fmaxf(b1, 0.f);
                    c0v = fmaxf(c0v, 0.f); c1 = fmaxf(c1, 0.f);
                    d0 = fmaxf(d0, 0.f); d1 = fmaxf(d1, 0.f);
                }
                q0 += (a0 + b0) + (c0v + d0);
                q1 += (a1 + b1) + (c1 + d1);
            }
            for (; j < end; j++) {
                const float* pa = hin + (size_t)csr_src[j] * 64;
                float a0 = pa[lane], a1 = pa[lane + 32];
                if (relu) { a0 = fmaxf(a0, 0.f); a1 = fmaxf(a1, 0.f); }
                q0 += a0;
                q1 += a1;
            }
            if (lane < 5) sv = S8[(size_t)n * 8 + lane];
        }
        qT[lane][nl] = q0;
        qT[lane + 32][nl] = q1;
        if (lane < 5) qT[64 + lane][nl] = sv;
        if (lane == 5) qT[69][nl] = deg;
    }
    __syncthreads();

    int tcol = t & 15, trow = t >> 4;
    int r0 = trow << 2, c0 = tcol << 2;
    ull acc[4][2];
    #pragma unroll
    for (int i = 0; i < 4; i++) { acc[i][0] = 0ull; acc[i][1] = 0ull; }

    #pragma unroll 10
    for (int k = 0; k < 70; k++) {
        float4 a = *(float4*)&qT[k][r0];
        const ull* bb = (const ull*)&Ws[k][c0];
        ull b0 = bb[0], b1 = bb[1];
        ull a0 = pk2(a.x), a1 = pk2(a.y), a2 = pk2(a.z), a3 = pk2(a.w);
        fma2(acc[0][0], a0, b0); fma2(acc[0][1], a0, b1);
        fma2(acc[1][0], a1, b0); fma2(acc[1][1], a1, b1);
        fma2(acc[2][0], a2, b0); fma2(acc[2][1], a2, b1);
        fma2(acc[3][0], a3, b0); fma2(acc[3][1], a3, b1);
    }

    #pragma unroll
    for (int i = 0; i < 4; i++) {
        int n = n0 + r0 + i;
        float2 p0 = up2(acc[i][0]), p1 = up2(acc[i][1]);
        if (n < NN)
            *(float4*)(out + (size_t)n * 64 + c0) = make_float4(p0.x, p0.y, p1.x, p1.y);
        if (attn) {
            float r0v = fmaxf(p0.x, 0.f), r1v = fmaxf(p0.y, 0.f);
            float r2v = fmaxf(p1.x, 0.f), r3v = fmaxf(p1.y, 0.f);
            float pS0 = r0v * sAv[c0] + r1v * sAv[c0 + 1] + r2v * sAv[c0 + 2] + r3v * sAv[c0 + 3];
            float pS1 = r0v * sAv[64 + c0] + r1v * sAv[64 + c0 + 1] + r2v * sAv[64 + c0 + 2] + r3v * sAv[64 + c0 + 3];
            float pD0 = r0v * sAv[128 + c0] + r1v * sAv[128 + c0 + 1] + r2v * sAv[128 + c0 + 2] + r3v * sAv[128 + c0 + 3];
            float pD1 = r0v * sAv[192 + c0] + r1v * sAv[192 + c0 + 1] + r2v * sAv[192 + c0 + 2] + r3v * sAv[192 + c0 + 3];
            #pragma unroll
            for (int o = 1; o < 16; o <<= 1) {
                pS0 += __shfl_xor_sync(0xffffffffu, pS0, o);
                pS1 += __shfl_xor_sync(0xffffffffu, pS1, o);
                pD0 += __shfl_xor_sync(0xffffffffu, pD0, o);
                pD1 += __shfl_xor_sync(0xffffffffu, pD1, o);
            }
            if (tcol == 0 && n < NN) {
                aS[n * 2] = pS0; aS[n * 2 + 1] = pS1;
                aD[n * 2] = pD0; aD[n * 2 + 1] = pD1;
            }
        }
    }
}

// ---------------- fused GAT: weighted gather -> smem zT -> mini-GEMM -> out ----------------
__global__ __launch_bounds__(256) void gat_fused(
    const int* __restrict__ csr_src, const int* __restrict__ rowptr,
    const float2* __restrict__ aS, const float2* __restrict__ aD,
    const float* __restrict__ h, const float* __restrict__ Wstk,
    const float* __restrict__ bias, float* __restrict__ out) {
    extern __shared__ float sm[];
    float* zT = sm;            // [128][68]
    float* Wc = sm + 128 * 68; // [64][64]
    int t = threadIdx.x;
    int n0 = blockIdx.x << 6;

    #pragma unroll
    for (int i = 0; i < 4; i++) {
        int idx = t + i * 256;
        int r = idx >> 4, c4 = (idx & 15) << 2;
        *(float4*)&Wc[r * 64 + c4] = *(const float4*)(Wstk + r * 64 + c4);
    }

    int w = t >> 5, lane = t & 31;
    #pragma unroll
    for (int i = 0; i < 8; i++) {
        int nl = w * 8 + i;
        int n = n0 + nl;
        float acc0 = 0.f, acc1 = 0.f, acc2 = 0.f, acc3 = 0.f;
        float id0 = 0.f, id1 = 0.f;
        if (n < NN) {
            int start = rowptr[n], end = rowptr[n + 1];
            float2 ad = aD[n];
            float m0 = -1e30f, m1 = -1e30f;
            for (int j = start + lane; j < end; j += 32) {
                float2 as = aS[csr_src[j]];
                m0 = fmaxf(m0, lrelu(as.x + ad.x));
                m1 = fmaxf(m1, lrelu(as.y + ad.y));
            }
            #pragma unroll
            for (int o = 16; o; o >>= 1) {
                m0 = fmaxf(m0, __shfl_xor_sync(0xffffffffu, m0, o));
                m1 = fmaxf(m1, __shfl_xor_sync(0xffffffffu, m1, o));
            }
            float den0 = 0.f, den1 = 0.f;
            int j = start;
            for (; j + 1 < end; j += 2) {
                int sA = csr_src[j], sB = csr_src[j + 1];
                float2 aA = aS[sA], aB = aS[sB];
                const float* hA = h + (size_t)sA * 64;
                const float* hB = h + (size_t)sB * 64;
                float vA0 = fmaxf(hA[lane], 0.f), vA1 = fmaxf(hA[lane + 32], 0.f);
                float vB0 = fmaxf(hB[lane], 0.f), vB1 = fmaxf(hB[lane + 32], 0.f);
                float wA0 = __expf(lrelu(aA.x + ad.x) - m0);
                float wA1 = __expf(lrelu(aA.y + ad.y) - m1);
                float wB0 = __expf(lrelu(aB.x + ad.x) - m0);
                float wB1 = __expf(lrelu(aB.y + ad.y) - m1);
                den0 += wA0 + wB0;
                den1 += wA1 + wB1;
                acc0 += wA0 * vA0 + wB0 * vB0;
                acc1 += wA0 * vA1 + wB0 * vB1;
                acc2 += wA1 * vA0 + wB1 * vB0;
                acc3 += wA1 * vA1 + wB1 * vB1;
            }
            if (j < end) {
                int sA = csr_src[j];
                float2 aA = aS[sA];
                const float* hA = h + (size_t)sA * 64;
                float vA0 = fmaxf(hA[lane], 0.f), vA1 = fmaxf(hA[lane + 32], 0.f);
                float wA0 = __expf(lrelu(aA.x + ad.x) - m0);
                float wA1 = __expf(lrelu(aA.y + ad.y) - m1);
                den0 += wA0;
                den1 += wA1;
                acc0 += wA0 * vA0;
                acc1 += wA0 * vA1;
                acc2 += wA1 * vA0;
                acc3 += wA1 * vA1;
            }
            id0 = 0.5f / (den0 + 1e-16f);
            id1 = 0.5f / (den1 + 1e-16f);
        }
        zT[(size_t)lane * 68 + nl] = acc0 * id0;
        zT[(size_t)(lane + 32) * 68 + nl] = acc1 * id0;
        zT[(size_t)(lane + 64) * 68 + nl] = acc2 * id1;
        zT[(size_t)(lane + 96) * 68 + nl] = acc3 * id1;
    }
    __syncthreads();

    int tcol = t & 15, trow = t >> 4;
    int r0 = trow << 2, c0 = tcol << 2;
    ull acc[4][2];
    #pragma unroll
    for (int i = 0; i < 4; i++) { acc[i][0] = 0ull; acc[i][1] = 0ull; }

    #pragma unroll 8
    for (int k = 0; k < 64; k++) {
        float4 a = *(float4*)&zT[k * 68 + r0];
        const ull* bb = (const ull*)&Wc[k * 64 + c0];
        ull b0 = bb[0], b1 = bb[1];
        ull a0 = pk2(a.x), a1 = pk2(a.y), a2 = pk2(a.z), a3 = pk2(a.w);
        fma2(acc[0][0], a0, b0); fma2(acc[0][1], a0, b1);
        fma2(acc[1][0], a1, b0); fma2(acc[1][1], a1, b1);
        fma2(acc[2][0], a2, b0); fma2(acc[2][1], a2, b1);
        fma2(acc[3][0], a3, b0); fma2(acc[3][1], a3, b1);
    }
    __syncthreads();
    #pragma unroll
    for (int i = 0; i < 4; i++) {
        int idx = t + i * 256;
        int r = idx >> 4, c4 = (idx & 15) << 2;
        *(float4*)&Wc[r * 64 + c4] = *(const float4*)(Wstk + (64 + r) * 64 + c4);
    }
    __syncthreads();
    #pragma unroll 8
    for (int k = 0; k < 64; k++) {
        float4 a = *(float4*)&zT[(64 + k) * 68 + r0];
        const ull* bb = (const ull*)&Wc[k * 64 + c0];
        ull b0 = bb[0], b1 = bb[1];
        ull a0 = pk2(a.x), a1 = pk2(a.y), a2 = pk2(a.z), a3 = pk2(a.w);
        fma2(acc[0][0], a0, b0); fma2(acc[0][1], a0, b1);
        fma2(acc[1][0], a1, b0); fma2(acc[1][1], a1, b1);
        fma2(acc[2][0], a2, b0); fma2(acc[2][1], a2, b1);
        fma2(acc[3][0], a3, b0); fma2(acc[3][1], a3, b1);
    }

    float4 bv = *(const float4*)(bias + c0);
    #pragma unroll
    for (int i = 0; i < 4; i++) {
        int n = n0 + r0 + i;
        if (n < NN) {
            float2 p0 = up2(acc[i][0]), p1 = up2(acc[i][1]);
            *(float4*)(out + (size_t)n * 64 + c0) =
                make_float4(p0.x + bv.x, p0.y + bv.y, p1.x + bv.z, p1.y + bv.w);
        }
    }
}

// ---------------- launch ----------------
extern "C" void kernel_launch(void* const* d_in, const int* in_sizes, int n_in,
                              void* d_out, int out_size) {
    const float* x = (const float*)d_in[0];
    const int* ei = (const int*)d_in[1];
    const float* ea = (const float*)d_in[2];
    const int* src = ei;
    const int* dst = ei + EE;
    FoldW fw;
    for (int i = 0; i < 18; i++) fw.w[i] = (const float*)d_in[3 + i];
    fw.wg = (const float*)d_in[21];
    fw.as = (const float*)d_in[22];
    fw.ad = (const float*)d_in[23];
    const float* b_gat = (const float*)d_in[24];
    float* out = (float*)d_out;

    float *h1, *h2, *h3, *asrc, *adst, *Wn, *We, *bp, *Wstk, *avec;
    float4* S4;
    int *cnt, *rowptr, *csr_src, *flag;
    cudaGetSymbolAddress((void**)&h1, g_h1);
    cudaGetSymbolAddress((void**)&h2, g_h2);
    cudaGetSymbolAddress((void**)&h3, g_h3);
    cudaGetSymbolAddress((void**)&asrc, g_asrc);
    cudaGetSymbolAddress((void**)&adst, g_adst);
    cudaGetSymbolAddress((void**)&Wn, g_Wn);
    cudaGetSymbolAddress((void**)&We, g_We);
    cudaGetSymbolAddress((void**)&bp, g_bp);
    cudaGetSymbolAddress((void**)&Wstk, g_Wstk);
    cudaGetSymbolAddress((void**)&avec, g_avec);
    cudaGetSymbolAddress((void**)&cnt, g_cnt);
    cudaGetSymbolAddress((void**)&rowptr, g_rowptr);
    cudaGetSymbolAddress((void**)&csr_src, g_csr_src);
    cudaGetSymbolAddress((void**)&S4, g_S4);
    cudaGetSymbolAddress((void**)&flag, g_scanflag);
    float* S8 = (float*)S4;

    static bool attr_done = false;
    if (!attr_done) {
        cudaFuncSetAttribute(gat_fused, cudaFuncAttributeMaxDynamicSharedMemorySize,
                             (128 * 68 + 64 * 64) * 4);
        attr_done = true;
    }

    const int FB = (NN + 63) / 64;   // 1563 blocks

    // ---- CSR build + weight folding ----
    zero_all<<<(NN * 2 + 255) / 256, 256>>>((int4*)cnt, S4, flag);
    count_fold<<<782 + 132, 256>>>(dst, cnt, fw, Wn, We, bp, Wstk, avec);
    scan_lb<<<SCAN_NB, 256>>>(cnt, flag, rowptr);
    scatter_kernel<<<(EE / 4 + 255) / 256, 256>>>(src, dst, rowptr, cnt, csr_src, ea, S8);

    // ---- 3 fused layers ----
    fused_layer<<<FB, 256>>>(x, csr_src, rowptr, S8, Wn + 0 * 4096, We + 0 * 320,
                             bp + 0 * 64, h1, 0, 0, avec, nullptr, nullptr);
    fused_layer<<<FB, 256>>>(h1, csr_src, rowptr, S8, Wn + 1 * 4096, We + 1 * 320,
                             bp + 1 * 64, h2, 1, 0, avec, nullptr, nullptr);
    fused_layer<<<FB, 256>>>(h2, csr_src, rowptr, S8, Wn + 2 * 4096, We + 2 * 320,
                             bp + 2 * 64, h3, 1, 1, avec, asrc, adst);

    // ---- fused GAT tail ----
    gat_fused<<<FB, 256, (128 * 68 + 64 * 64) * 4>>>(
        csr_src, rowptr, (const float2*)asrc, (const float2*)adst,
        h3, Wstk, b_gat, out);
}

// round 16
// speedup vs baseline: 1.1163x; 1.0543x over previous
#include <cuda_runtime.h>

#define NN 100000
#define EE 800000
#define SCAN_NB 98   // 98*1024 = 100352 >= NN

typedef unsigned long long ull;

// ---------------- scratch (device globals) ----------------
__device__ float g_h1[NN * 64];
__device__ float g_h2[NN * 64];
__device__ float g_h3[NN * 64];
__device__ float g_asrc[NN * 2];
__device__ float g_adst[NN * 2];
__device__ float g_Wn[3][4096];
__device__ float g_We[3][320];
__device__ float g_bp[3][64];
__device__ float g_Wstk[8192];     // [k][c]: k<64 -> Wg[k][c] ; k>=64 -> Wg[k-64][64+c]
__device__ float g_avec[256];      // avS0[64] avS1[64] avD0[64] avD1[64]
__device__ int g_cnt[NN];
__device__ int g_rowptr[NN + 4];
__device__ int g_csr_src[EE];
__device__ float4 g_S4[NN * 2];    // S padded to 8 floats/node
__device__ int g_scanflag[SCAN_NB];

__device__ __forceinline__ float lrelu(float x) { return x > 0.f ? x : 0.2f * x; }

__device__ __forceinline__ ull pk2(float x) {
    ull r; asm("mov.b64 %0,{%1,%1};" : "=l"(r) : "f"(x)); return r;
}
__device__ __forceinline__ void fma2(ull& d, ull a, ull b) {
    asm("fma.rn.f32x2 %0,%1,%2,%0;" : "+l"(d) : "l"(a), "l"(b));
}
__device__ __forceinline__ float2 up2(ull v) {
    float2 r; asm("mov.b64 {%0,%1},%2;" : "=f"(r.x), "=f"(r.y) : "l"(v)); return r;
}

// ---------------- zero scratch ----------------
__global__ void zero_all(int4* __restrict__ cnt4, float4* __restrict__ S4,
                         int* __restrict__ flag) {
    int i = blockIdx.x * blockDim.x + threadIdx.x;
    if (i < NN / 4) cnt4[i] = make_int4(0, 0, 0, 0);
    if (i < NN * 2) S4[i] = make_float4(0.f, 0.f, 0.f, 0.f);
    if (i < SCAN_NB) flag[i] = 0;
}

// ---------------- count (blocks 0..781) + weight fold (blocks 782..913) ----------------
struct FoldW { const float* w[18]; const float* wg; const float* as; const float* ad; };

__global__ void count_fold(const int* __restrict__ dst, int* __restrict__ cnt,
                           FoldW fw, float* __restrict__ Wn, float* __restrict__ We,
                           float* __restrict__ bp, float* __restrict__ Wstk,
                           float* __restrict__ avec) {
    int b = blockIdx.x;
    if (b < 782) {
        int i = b * 256 + threadIdx.x;
        if (i * 4 >= EE) return;
        int4 d = ((const int4*)dst)[i];
        atomicAdd(&cnt[d.x], 1);
        atomicAdd(&cnt[d.y], 1);
        atomicAdd(&cnt[d.z], 1);
        atomicAdd(&cnt[d.w], 1);
        return;
    }
    int fb = b - 782;
    int L = fb / 33;
    int t = (fb % 33) * 256 + threadIdx.x;
    if (L < 3) {
        if (t >= 4480) return;
        const float* wn = fw.w[6 * L + 0];
        const float* bn = fw.w[6 * L + 1];
        const float* we = fw.w[6 * L + 2];
        const float* be = fw.w[6 * L + 3];
        const float* wc = fw.w[6 * L + 4];
        const float* bc = fw.w[6 * L + 5];
        if (t < 4096) {
            int r = t >> 6, c = t & 63;
            float s = 0.f;
            #pragma unroll 8
            for (int k = 0; k < 64; k++) s += wn[r * 64 + k] * wc[k * 64 + c];
            Wn[L * 4096 + t] = s;
        } else if (t < 4416) {
            int u = t - 4096;
            int j = u >> 6, c = u & 63;
            float s = 0.f;
            #pragma unroll 8
            for (int k = 0; k < 64; k++) s += we[j * 64 + k] * wc[(64 + k) * 64 + c];
            We[L * 320 + u] = s;
        } else {
            int c = t - 4416;
            float s = bc[c];
            #pragma unroll 8
            for (int k = 0; k < 64; k++)
                s += bn[k] * wc[k * 64 + c] + be[k] * wc[(64 + k) * 64 + c];
            bp[L * 64 + c] = s;
        }
    } else {
        if (t < 8192) {
            int k = t >> 6, c = t & 63;
            Wstk[t] = (k < 64) ? fw.wg[k * 128 + c] : fw.wg[(k - 64) * 128 + 64 + c];
        } else if (t < 8448) {
            int u = t - 8192;
            int vec = u >> 6;
            int k = u & 63;
            int hd = vec & 1;
            const float* att = (vec < 2) ? fw.as : fw.ad;
            float s = 0.f;
            #pragma unroll 8
            for (int c = 0; c < 64; c++) s += fw.wg[k * 128 + hd * 64 + c] * att[hd * 64 + c];
            avec[u] = s;
        }
    }
}

// ---------------- single-kernel scan ----------------
__global__ void scan_lb(const int* __restrict__ cnt, int* __restrict__ flag,
                        int* __restrict__ rowptr) {
    __shared__ int wsum[8];
    __shared__ int offsum[8];
    __shared__ int s_boff;
    int b = blockIdx.x, t = threadIdx.x;
    int lane = t & 31, wid = t >> 5;
    int idx = b * 1024 + t * 4;
    int v[4] = {0, 0, 0, 0};
    if (idx < NN) {
        int4 d = *(const int4*)(cnt + idx);
        v[0] = d.x; v[1] = d.y; v[2] = d.z; v[3] = d.w;
    }
    #pragma unroll
    for (int j = 1; j < 4; j++) v[j] += v[j - 1];
    int tot = v[3];
    int incl = tot;
    #pragma unroll
    for (int o = 1; o < 32; o <<= 1) {
        int u = __shfl_up_sync(0xffffffffu, incl, o);
        if (lane >= o) incl += u;
    }
    if (lane == 31) wsum[wid] = incl;
    __syncthreads();
    if (t == 0) {
        int bt = 0;
        #pragma unroll
        for (int w = 0; w < 8; w++) bt += wsum[w];
        atomicExch(&flag[b], bt + 1);
    }
    int agg = 0;
    if (t < b) {
        volatile int* vf = (volatile int*)flag;
        int val;
        do { val = vf[t]; } while (val == 0);
        agg = val - 1;
    }
    #pragma unroll
    for (int o = 16; o; o >>= 1) agg += __shfl_xor_sync(0xffffffffu, agg, o);
    if (lane == 0) offsum[wid] = agg;
    __syncthreads();
    if (t == 0) {
        int bo = 0;
        #pragma unroll
        for (int w = 0; w < 8; w++) bo += offsum[w];
        s_boff = bo;
    }
    __syncthreads();
    int woff = 0;
    for (int w = 0; w < wid; w++) woff += wsum[w];
    int excl = s_boff + woff + incl - tot;
    if (idx < NN) {
        #pragma unroll
        for (int j = 0; j < 4; j++) rowptr[idx + j + 1] = excl + v[j];
    }
    if (b == 0 && t == 0) rowptr[0] = 0;
}

// ---------------- scatter: countdown + csr_src store + vectorized S reduction ----------------
__device__ __forceinline__ void scat1(int d, int s, int e, const int* __restrict__ rowptr,
                                      int* __restrict__ cnt, int* __restrict__ csr_src,
                                      const float* __restrict__ ea, float* __restrict__ S8) {
    int pos = atomicAdd(&cnt[d], -1) - 1;
    csr_src[rowptr[d] + pos] = s;
    const float* eap = ea + (size_t)e * 5;
    float e0 = eap[0], e1 = eap[1], e2 = eap[2], e3 = eap[3], e4 = eap[4];
    float* sp = S8 + (size_t)d * 8;
    asm volatile("red.global.add.v4.f32 [%0], {%1,%2,%3,%4};"
                 :: "l"(sp), "f"(e0), "f"(e1), "f"(e2), "f"(e3) : "memory");
    atomicAdd(sp + 4, e4);
}

__global__ void scatter_kernel(const int* __restrict__ src, const int* __restrict__ dst,
                               const int* __restrict__ rowptr, int* __restrict__ cnt,
                               int* __restrict__ csr_src, const float* __restrict__ ea,
                               float* __restrict__ S8) {
    int i = blockIdx.x * blockDim.x + threadIdx.x;
    if (i * 4 >= EE) return;
    int4 d4 = ((const int4*)dst)[i];
    int4 s4 = ((const int4*)src)[i];
    int e = i * 4;
    scat1(d4.x, s4.x, e + 0, rowptr, cnt, csr_src, ea, S8);
    scat1(d4.y, s4.y, e + 1, rowptr, cnt, csr_src, ea, S8);
    scat1(d4.z, s4.z, e + 2, rowptr, cnt, csr_src, ea, S8);
    scat1(d4.w, s4.w, e + 3, rowptr, cnt, csr_src, ea, S8);
}

// ---------------- fused layer: gather (inputs pre-relu'd) + mini-GEMM, store relu'd ----------------
__global__ __launch_bounds__(256) void fused_layer(
    const float* __restrict__ hin, const int* __restrict__ csr_src,
    const int* __restrict__ rowptr, const float* __restrict__ S8,
    const float* __restrict__ Wn, const float* __restrict__ We,
    const float* __restrict__ bp, float* __restrict__ out,
    int attn, const float* __restrict__ avec,
    float* __restrict__ aS, float* __restrict__ aD) {
    __shared__ float qT[70][68];
    __shared__ float Ws[70][64];
    __shared__ float sAv[256];
    int t = threadIdx.x;
    int n0 = blockIdx.x << 6;

    #pragma unroll
    for (int i = 0; i < 5; i++) {
        int idx = t + i * 256;
        if (idx < 1120) {
            int r = idx >> 4, c4 = (idx & 15) << 2;
            float4 v;
            if (r < 64) v = *(const float4*)(Wn + r * 64 + c4);
            else if (r < 69) v = *(const float4*)(We + (r - 64) * 64 + c4);
            else v = *(const float4*)(bp + c4);
            *(float4*)&Ws[r][c4] = v;
        }
    }
    if (attn) sAv[t] = avec[t];

    int w = t >> 5, lane = t & 31;
    #pragma unroll
    for (int i = 0; i < 8; i++) {
        int nl = w * 8 + i;
        int n = n0 + nl;
        float q0 = 0.f, q1 = 0.f, deg = 0.f, sv = 0.f;
        if (n < NN) {
            int start = rowptr[n], end = rowptr[n + 1];
            deg = (float)(end - start);
            int j = start;
            for (; j + 3 < end; j += 4) {
                const float* pa = hin + (size_t)csr_src[j] * 64;
                const float* pb = hin + (size_t)csr_src[j + 1] * 64;
                const float* pc = hin + (size_t)csr_src[j + 2] * 64;
                const float* pd = hin + (size_t)csr_src[j + 3] * 64;
                q0 += (pa[lane] + pb[lane]) + (pc[lane] + pd[lane]);
                q1 += (pa[lane + 32] + pb[lane + 32]) + (pc[lane + 32] + pd[lane + 32]);
            }
            for (; j < end; j++) {
                const float* pa = hin + (size_t)csr_src[j] * 64;
                q0 += pa[lane];
                q1 += pa[lane + 32];
            }
            if (lane < 5) sv = S8[(size_t)n * 8 + lane];
        }
        qT[lane][nl] = q0;
        qT[lane + 32][nl] = q1;
        if (lane < 5) qT[64 + lane][nl] = sv;
        if (lane == 5) qT[69][nl] = deg;
    }
    __syncthreads();

    int tcol = t & 15, trow = t >> 4;
    int r0 = trow << 2, c0 = tcol << 2;
    ull acc[4][2];
    #pragma unroll
    for (int i = 0; i < 4; i++) { acc[i][0] = 0ull; acc[i][1] = 0ull; }

    #pragma unroll 10
    for (int k = 0; k < 70; k++) {
        float4 a = *(float4*)&qT[k][r0];
        const ull* bb = (const ull*)&Ws[k][c0];
        ull b0 = bb[0], b1 = bb[1];
        ull a0 = pk2(a.x), a1 = pk2(a.y), a2 = pk2(a.z), a3 = pk2(a.w);
        fma2(acc[0][0], a0, b0); fma2(acc[0][1], a0, b1);
        fma2(acc[1][0], a1, b0); fma2(acc[1][1], a1, b1);
        fma2(acc[2][0], a2, b0); fma2(acc[2][1], a2, b1);
        fma2(acc[3][0], a3, b0); fma2(acc[3][1], a3, b1);
    }

    #pragma unroll
    for (int i = 0; i < 4; i++) {
        int n = n0 + r0 + i;
        float2 p0 = up2(acc[i][0]), p1 = up2(acc[i][1]);
        // store relu'd: every consumer (next-layer gather, attn, gat) wants relu(h)
        float r0v = fmaxf(p0.x, 0.f), r1v = fmaxf(p0.y, 0.f);
        float r2v = fmaxf(p1.x, 0.f), r3v = fmaxf(p1.y, 0.f);
        if (n < NN)
            *(float4*)(out + (size_t)n * 64 + c0) = make_float4(r0v, r1v, r2v, r3v);
        if (attn) {
            float pS0 = r0v * sAv[c0] + r1v * sAv[c0 + 1] + r2v * sAv[c0 + 2] + r3v * sAv[c0 + 3];
            float pS1 = r0v * sAv[64 + c0] + r1v * sAv[64 + c0 + 1] + r2v * sAv[64 + c0 + 2] + r3v * sAv[64 + c0 + 3];
            float pD0 = r0v * sAv[128 + c0] + r1v * sAv[128 + c0 + 1] + r2v * sAv[128 + c0 + 2] + r3v * sAv[128 + c0 + 3];
            float pD1 = r0v * sAv[192 + c0] + r1v * sAv[192 + c0 + 1] + r2v * sAv[192 + c0 + 2] + r3v * sAv[192 + c0 + 3];
            #pragma unroll
            for (int o = 1; o < 16; o <<= 1) {
                pS0 += __shfl_xor_sync(0xffffffffu, pS0, o);
                pS1 += __shfl_xor_sync(0xffffffffu, pS1, o);
                pD0 += __shfl_xor_sync(0xffffffffu, pD0, o);
                pD1 += __shfl_xor_sync(0xffffffffu, pD1, o);
            }
            if (tcol == 0 && n < NN) {
                aS[n * 2] = pS0; aS[n * 2 + 1] = pS1;
                aD[n * 2] = pD0; aD[n * 2 + 1] = pD1;
            }
        }
    }
}

// ---------------- fused GAT: shfl-cached softmax gather -> smem zT -> mini-GEMM -> out ----------------
__global__ __launch_bounds__(256) void gat_fused(
    const int* __restrict__ csr_src, const int* __restrict__ rowptr,
    const float2* __restrict__ aS, const float2* __restrict__ aD,
    const float* __restrict__ h, const float* __restrict__ Wstk,
    const float* __restrict__ bias, float* __restrict__ out) {
    extern __shared__ float sm[];
    float* zT = sm;            // [128][68]
    float* Wc = sm + 128 * 68; // [64][64]
    int t = threadIdx.x;
    int n0 = blockIdx.x << 6;

    #pragma unroll
    for (int i = 0; i < 4; i++) {
        int idx = t + i * 256;
        int r = idx >> 4, c4 = (idx & 15) << 2;
        *(float4*)&Wc[r * 64 + c4] = *(const float4*)(Wstk + r * 64 + c4);
    }

    int w = t >> 5, lane = t & 31;
    #pragma unroll
    for (int i = 0; i < 8; i++) {
        int nl = w * 8 + i;
        int n = n0 + nl;
        float acc0 = 0.f, acc1 = 0.f, acc2 = 0.f, acc3 = 0.f;
        float id0 = 0.f, id1 = 0.f;
        if (n < NN) {
            int start = rowptr[n], end = rowptr[n + 1];
            int deg = end - start;
            float2 ad = aD[n];
            // pass 1: lane-parallel load of first 32 edges, kept in registers
            int sl = 0;
            float a0l = -1e30f, a1l = -1e30f;
            if (lane < deg) {
                sl = csr_src[start + lane];
                float2 as = aS[sl];
                a0l = lrelu(as.x + ad.x);
                a1l = lrelu(as.y + ad.y);
            }
            float m0 = a0l, m1 = a1l;
            for (int j = start + 32 + lane; j < end; j += 32) {   // deg>32: ~never
                float2 as = aS[csr_src[j]];
                m0 = fmaxf(m0, lrelu(as.x + ad.x));
                m1 = fmaxf(m1, lrelu(as.y + ad.y));
            }
            #pragma unroll
            for (int o = 16; o; o >>= 1) {
                m0 = fmaxf(m0, __shfl_xor_sync(0xffffffffu, m0, o));
                m1 = fmaxf(m1, __shfl_xor_sync(0xffffffffu, m1, o));
            }
            // per-lane weights (first 32 edges)
            float w0l = 0.f, w1l = 0.f;
            if (lane < deg) {
                w0l = __expf(a0l - m0);
                w1l = __expf(a1l - m1);
            }
            float den0 = w0l, den1 = w1l;
            // pass 2: shfl-broadcast, no reloads
            int jmax = min(deg, 32);
            for (int j = 0; j < jmax; j++) {
                float w0 = __shfl_sync(0xffffffffu, w0l, j);
                float w1 = __shfl_sync(0xffffffffu, w1l, j);
                int s = __shfl_sync(0xffffffffu, sl, j);
                const float* hs = h + (size_t)s * 64;
                float v0 = hs[lane], v1 = hs[lane + 32];
                acc0 += w0 * v0;
                acc1 += w0 * v1;
                acc2 += w1 * v0;
                acc3 += w1 * v1;
            }
            // fallback for deg > 32 (essentially never with avg degree 8)
            for (int j = start + 32; j < end; j++) {
                int s = csr_src[j];
                float2 as = aS[s];
                float w0 = __expf(lrelu(as.x + ad.x) - m0);
                float w1 = __expf(lrelu(as.y + ad.y) - m1);
                if (lane == 0) { den0 += w0; den1 += w1; }
                const float* hs = h + (size_t)s * 64;
                float v0 = hs[lane], v1 = hs[lane + 32];
                acc0 += w0 * v0;
                acc1 += w0 * v1;
                acc2 += w1 * v0;
                acc3 += w1 * v1;
            }
            #pragma unroll
            for (int o = 16; o; o >>= 1) {
                den0 += __shfl_xor_sync(0xffffffffu, den0, o);
                den1 += __shfl_xor_sync(0xffffffffu, den1, o);
            }
            id0 = 0.5f / (den0 + 1e-16f);
            id1 = 0.5f / (den1 + 1e-16f);
        }
        zT[(size_t)lane * 68 + nl] = acc0 * id0;
        zT[(size_t)(lane + 32) * 68 + nl] = acc1 * id0;
        zT[(size_t)(lane + 64) * 68 + nl] = acc2 * id1;
        zT[(size_t)(lane + 96) * 68 + nl] = acc3 * id1;
    }
    __syncthreads();

    int tcol = t & 15, trow = t >> 4;
    int r0 = trow << 2, c0 = tcol << 2;
    ull acc[4][2];
    #pragma unroll
    for (int i = 0; i < 4; i++) { acc[i][0] = 0ull; acc[i][1] = 0ull; }

    #pragma unroll 8
    for (int k = 0; k < 64; k++) {
        float4 a = *(float4*)&zT[k * 68 + r0];
        const ull* bb = (const ull*)&Wc[k * 64 + c0];
        ull b0 = bb[0], b1 = bb[1];
        ull a0 = pk2(a.x), a1 = pk2(a.y), a2 = pk2(a.z), a3 = pk2(a.w);
        fma2(acc[0][0], a0, b0); fma2(acc[0][1], a0, b1);
        fma2(acc[1][0], a1, b0); fma2(acc[1][1], a1, b1);
        fma2(acc[2][0], a2, b0); fma2(acc[2][1], a2, b1);
        fma2(acc[3][0], a3, b0); fma2(acc[3][1], a3, b1);
    }
    __syncthreads();
    #pragma unroll
    for (int i = 0; i < 4; i++) {
        int idx = t + i * 256;
        int r = idx >> 4, c4 = (idx & 15) << 2;
        *(float4*)&Wc[r * 64 + c4] = *(const float4*)(Wstk + (64 + r) * 64 + c4);
    }
    __syncthreads();
    #pragma unroll 8
    for (int k = 0; k < 64; k++) {
        float4 a = *(float4*)&zT[(64 + k) * 68 + r0];
        const ull* bb = (const ull*)&Wc[k * 64 + c0];
        ull b0 = bb[0], b1 = bb[1];
        ull a0 = pk2(a.x), a1 = pk2(a.y), a2 = pk2(a.z), a3 = pk2(a.w);
        fma2(acc[0][0], a0, b0); fma2(acc[0][1], a0, b1);
        fma2(acc[1][0], a1, b0); fma2(acc[1][1], a1, b1);
        fma2(acc[2][0], a2, b0); fma2(acc[2][1], a2, b1);
        fma2(acc[3][0], a3, b0); fma2(acc[3][1], a3, b1);
    }

    float4 bv = *(const float4*)(bias + c0);
    #pragma unroll
    for (int i = 0; i < 4; i++) {
        int n = n0 + r0 + i;
        if (n < NN) {
            float2 p0 = up2(acc[i][0]), p1 = up2(acc[i][1]);
            *(float4*)(out + (size_t)n * 64 + c0) =
                make_float4(p0.x + bv.x, p0.y + bv.y, p1.x + bv.z, p1.y + bv.w);
        }
    }
}

// ---------------- launch ----------------
extern "C" void kernel_launch(void* const* d_in, const int* in_sizes, int n_in,
                              void* d_out, int out_size) {
    const float* x = (const float*)d_in[0];
    const int* ei = (const int*)d_in[1];
    const float* ea = (const float*)d_in[2];
    const int* src = ei;
    const int* dst = ei + EE;
    FoldW fw;
    for (int i = 0; i < 18; i++) fw.w[i] = (const float*)d_in[3 + i];
    fw.wg = (const float*)d_in[21];
    fw.as = (const float*)d_in[22];
    fw.ad = (const float*)d_in[23];
    const float* b_gat = (const float*)d_in[24];
    float* out = (float*)d_out;

    float *h1, *h2, *h3, *asrc, *adst, *Wn, *We, *bp, *Wstk, *avec;
    float4* S4;
    int *cnt, *rowptr, *csr_src, *flag;
    cudaGetSymbolAddress((void**)&h1, g_h1);
    cudaGetSymbolAddress((void**)&h2, g_h2);
    cudaGetSymbolAddress((void**)&h3, g_h3);
    cudaGetSymbolAddress((void**)&asrc, g_asrc);
    cudaGetSymbolAddress((void**)&adst, g_adst);
    cudaGetSymbolAddress((void**)&Wn, g_Wn);
    cudaGetSymbolAddress((void**)&We, g_We);
    cudaGetSymbolAddress((void**)&bp, g_bp);
    cudaGetSymbolAddress((void**)&Wstk, g_Wstk);
    cudaGetSymbolAddress((void**)&avec, g_avec);
    cudaGetSymbolAddress((void**)&cnt, g_cnt);
    cudaGetSymbolAddress((void**)&rowptr, g_rowptr);
    cudaGetSymbolAddress((void**)&csr_src, g_csr_src);
    cudaGetSymbolAddress((void**)&S4, g_S4);
    cudaGetSymbolAddress((void**)&flag, g_scanflag);
    float* S8 = (float*)S4;

    static bool attr_done = false;
    if (!attr_done) {
        cudaFuncSetAttribute(gat_fused, cudaFuncAttributeMaxDynamicSharedMemorySize,
                             (128 * 68 + 64 * 64) * 4);
        attr_done = true;
    }

    const int FB = (NN + 63) / 64;   // 1563 blocks

    // ---- CSR build + weight folding ----
    zero_all<<<(NN * 2 + 255) / 256, 256>>>((int4*)cnt, S4, flag);
    count_fold<<<782 + 132, 256>>>(dst, cnt, fw, Wn, We, bp, Wstk, avec);
    scan_lb<<<SCAN_NB, 256>>>(cnt, flag, rowptr);
    scatter_kernel<<<(EE / 4 + 255) / 256, 256>>>(src, dst, rowptr, cnt, csr_src, ea, S8);

    // ---- 3 fused layers (outputs stored relu'd; gathers read relu'd directly) ----
    fused_layer<<<FB, 256>>>(x, csr_src, rowptr, S8, Wn + 0 * 4096, We + 0 * 320,
                             bp + 0 * 64, h1, 0, avec, nullptr, nullptr);
    fused_layer<<<FB, 256>>>(h1, csr_src, rowptr, S8, Wn + 1 * 4096, We + 1 * 320,
                             bp + 1 * 64, h2, 0, avec, nullptr, nullptr);
    fused_layer<<<FB, 256>>>(h2, csr_src, rowptr, S8, Wn + 2 * 4096, We + 2 * 320,
                             bp + 2 * 64, h3, 1, avec, asrc, adst);

    // ---- fused GAT tail ----
    gat_fused<<<FB, 256, (128 * 68 + 64 * 64) * 4>>>(
        csr_src, rowptr, (const float2*)asrc, (const float2*)adst,
        h3, Wstk, b_gat, out);
}